// round 15
// baseline (speedup 1.0000x reference)
#include <cuda_runtime.h>
#include <cuda_fp16.h>
#include <cstdint>

#define Bb 2048
#define Nn 512
#define Hh 20
#define Tt 3
#define BH (Bb * Hh)          // 40960 columns

typedef unsigned long long u64;
typedef unsigned int u32;

// ---------------- device scratch ----------------
__device__ __half g_Ast[2 * Nn * Nn];         // stacked [A; A^T] fp16, [1024][512]
// Unified per-batch operand tensor: [b][64 rows][512 nodes] fp16
//   rows 0-19: agg_in, 20-39: agg_out, 40-59: fn (state), 60-63: zeros
__device__ __half g_D[(size_t)Bb * 64 * Nn];
__device__ __half g_xout[(size_t)Bb * Hh * Nn]; // Wout[:,20:40]@x + b, fp16 [b][h][n]
__device__ __half g_Wcat[64 * 64];            // [Wz;Wr;Wh_av] padded, [m][k] fp16

// ---------------- helpers ----------------
__device__ __forceinline__ u32 smem_u32(const void* p) {
    u32 a; asm("{ .reg .u64 t; cvta.to.shared.u64 t, %1; cvt.u32.u64 %0, t; }"
               : "=r"(a) : "l"(p)); return a;
}
__device__ __forceinline__ u64 pack2(float lo, float hi) {
    u64 r; asm("mov.b64 %0, {%1, %2};" : "=l"(r) : "f"(lo), "f"(hi)); return r;
}
__device__ __forceinline__ void unpack2(u64 v, float& lo, float& hi) {
    asm("mov.b64 {%0, %1}, %2;" : "=f"(lo), "=f"(hi) : "l"(v));
}
__device__ __forceinline__ u64 fma2(u64 a, u64 b, u64 c) {
    u64 d; asm("fma.rn.f32x2 %0, %1, %2, %3;" : "=l"(d) : "l"(a), "l"(b), "l"(c)); return d;
}
__device__ __forceinline__ float fsum2(u64 v) { float a, b; unpack2(v, a, b); return a + b; }

__device__ __forceinline__ float tanh_fast(float x) {
    float y; asm("tanh.approx.f32 %0, %1;" : "=f"(y) : "f"(x)); return y;
}
__device__ __forceinline__ float sigmoid_fast(float x) {
    return fmaf(tanh_fast(0.5f * x), 0.5f, 0.5f);
}

__device__ __forceinline__ void cp16(u32 dst, const void* src) {
    asm volatile("cp.async.cg.shared.global [%0], [%1], 16;" :: "r"(dst), "l"(src) : "memory");
}
#define CP_COMMIT() asm volatile("cp.async.commit_group;" ::: "memory")
#define CP_WAIT1()  asm volatile("cp.async.wait_group 1;" ::: "memory")
#define CP_WAIT0()  asm volatile("cp.async.wait_group 0;" ::: "memory")

__device__ __forceinline__ void ldsm4(u32& r0, u32& r1, u32& r2, u32& r3, u32 addr) {
    asm volatile("ldmatrix.sync.aligned.m8n8.x4.shared.b16 {%0,%1,%2,%3}, [%4];"
                 : "=r"(r0), "=r"(r1), "=r"(r2), "=r"(r3) : "r"(addr));
}
__device__ __forceinline__ void ldsm4t(u32& r0, u32& r1, u32& r2, u32& r3, u32 addr) {
    asm volatile("ldmatrix.sync.aligned.m8n8.x4.trans.shared.b16 {%0,%1,%2,%3}, [%4];"
                 : "=r"(r0), "=r"(r1), "=r"(r2), "=r"(r3) : "r"(addr));
}
__device__ __forceinline__ void mma16816(float* c,
                                         u32 a0, u32 a1, u32 a2, u32 a3, u32 b0, u32 b1) {
    asm volatile("mma.sync.aligned.m16n8k16.row.col.f32.f16.f16.f32 "
                 "{%0,%1,%2,%3}, {%4,%5,%6,%7}, {%8,%9}, {%0,%1,%2,%3};"
                 : "+f"(c[0]), "+f"(c[1]), "+f"(c[2]), "+f"(c[3])
                 : "r"(a0), "r"(a1), "r"(a2), "r"(a3), "r"(b0), "r"(b1));
}

// ---------------- prep: A -> fp16 stacked [A; A^T] ----------------
__global__ void conv_A_kernel(const float* __restrict__ A) {
    __shared__ float t[32][33];
    int x = blockIdx.x * 32 + threadIdx.x;
    int y = blockIdx.y * 32 + threadIdx.y;
    float v = A[y * Nn + x];
    g_Ast[y * Nn + x] = __float2half(v);
    t[threadIdx.y][threadIdx.x] = v;
    __syncthreads();
    int xo = blockIdx.y * 32 + threadIdx.x;
    int yo = blockIdx.x * 32 + threadIdx.y;
    g_Ast[(Nn + yo) * Nn + xo] = __float2half(t[threadIdx.x][threadIdx.y]);
}

// ---------------- prep: Wcat [64 m][64 k] fp16 ----------------
__global__ void conv_W_kernel(const float* __restrict__ W3w, const float* __restrict__ W3u,
                              const float* __restrict__ W4w, const float* __restrict__ W4u,
                              const float* __restrict__ W5w) {
    int idx = blockIdx.x * 256 + threadIdx.x;   // 0..4095
    int m = idx >> 6, k = idx & 63;
    float v = 0.f;
    if (m < 20) {
        if (k < 40) v = W3w[m * 40 + k];
        else if (k < 60) v = W3u[m * 20 + (k - 40)];
    } else if (m < 40) {
        int h = m - 20;
        if (k < 40) v = W4w[h * 40 + k];
        else if (k < 60) v = W4u[h * 20 + (k - 40)];
    } else if (m < 60) {
        int h = m - 40;
        if (k < 40) v = W5w[h * 40 + k];
    }
    g_Wcat[idx] = __float2half(v);
}

// ---------------- prep: x -> fn/pad rows of g_D + g_xout (coalesced) -------
__global__ void __launch_bounds__(Nn) conv_X_kernel(const float* __restrict__ x,
                                                    const float* __restrict__ Wout,
                                                    const float* __restrict__ bout) {
    __shared__ float sx[Nn * Hh];          // 40 KB, [node][h]
    __shared__ float sWo2[Hh][Hh];
    __shared__ float sB[Hh];
    int b = blockIdx.x, n = threadIdx.x;
    for (int i = n; i < Hh * Hh; i += Nn) sWo2[i / Hh][i % Hh] = Wout[(i / Hh) * 40 + 20 + (i % Hh)];
    if (n < Hh) sB[n] = bout[n];
    // coalesced stage of x[b] (2560 float4s)
    {
        const float4* src = (const float4*)(x + (size_t)b * Nn * Hh);
        float4* dst = (float4*)sx;
        #pragma unroll
        for (int i = 0; i < 5; i++) dst[n + i * Nn] = src[n + i * Nn];
    }
    __syncthreads();

    float v[Hh];
    {
        const float4* xp = (const float4*)(sx + n * Hh);
        #pragma unroll
        for (int j = 0; j < 5; j++) {
            float4 q = xp[j];
            v[4 * j] = q.x; v[4 * j + 1] = q.y; v[4 * j + 2] = q.z; v[4 * j + 3] = q.w;
        }
    }
    const size_t sb = (size_t)b * Hh * Nn + n;
    const size_t db = (size_t)b * 64 * Nn + n;
    #pragma unroll
    for (int h = 0; h < Hh; h++) {
        g_D[db + (size_t)(40 + h) * Nn] = __float2half(v[h]);
        float s = sB[h];
        #pragma unroll
        for (int j = 0; j < Hh; j++) s = fmaf(sWo2[h][j], v[j], s);
        g_xout[sb + (size_t)h * Nn] = __float2half(s);
    }
    #pragma unroll
    for (int r = 60; r < 64; r++) g_D[db + (size_t)r * Nn] = __float2half(0.f);
}

// ---------------- HMMA GEMM: [A;A^T] @ X -> g_D rows 0-39 (fp16) ----------
// 128-thread CTAs, 4 CTAs/SM. CTA tile 128m x 64n, K-chunk 64, 2-stage.
// stage: A 128x64 @ +0 (16 KB), X 64x64 @ +16384 (8 KB) -> 24 KB/stage.
#define STAGE_B 24576
#define TRH 136   // transpose buffer stride (halfs)

__global__ void __launch_bounds__(128, 4) gemm_kernel() {
    extern __shared__ char smraw[];
    char* smg = (char*)(((uintptr_t)smraw + 127) & ~(uintptr_t)127);
    const u32 smem = smem_u32(smg);
    const int tid = threadIdx.x;
    const int wid = tid >> 5;        // 0..3
    const int lane = tid & 31;
    const int ntile = blockIdx.x;    // 0..639 (64 cols each)
    const int mtile = blockIdx.y;    // 0..7  (<4: agg_in, >=4: agg_out)

    const int m_off = (wid & 1) * 64;
    const int n_off = (wid >> 1) * 32;

    auto load_stage = [&](int kc, int s) {
        const u32 base = smem + (u32)s * STAGE_B;
        #pragma unroll
        for (int i = 0; i < 12; i++) {
            int idx = tid + i * 128;       // 0..1535
            const __half* src;
            u32 dst;
            if (idx < 1024) {              // A: 128 rows x 8 chunks
                int r = idx >> 3, c = idx & 7;
                dst = base + r * 128 + (u32)((c ^ (r & 7)) << 4);
                src = g_Ast + (size_t)(mtile * 128 + r) * Nn + kc * 64 + c * 8;
            } else {                       // X: 64 cols x 8 chunks
                int j = idx - 1024;
                int r = j >> 3, c = j & 7;
                dst = base + 16384 + r * 128 + (u32)((c ^ (r & 7)) << 4);
                int col = ntile * 64 + r;
                int bb = col / 20, hh = col - bb * 20;
                src = g_D + (size_t)bb * 64 * Nn + (size_t)(40 + hh) * Nn + kc * 64 + c * 8;
            }
            cp16(dst, src);
        }
        CP_COMMIT();
    };

    float c[4][4][4];
    #pragma unroll
    for (int mt = 0; mt < 4; mt++)
        #pragma unroll
        for (int nt = 0; nt < 4; nt++)
            #pragma unroll
            for (int q = 0; q < 4; q++) c[mt][nt][q] = 0.f;

    const int rA = m_off + (lane & 15);
    const int cA = lane >> 4;
    const int sA = rA & 7;
    const int rB = n_off + ((lane >> 4) & 1) * 8 + (lane & 7);
    const int cB = (lane >> 3) & 1;
    const int sB = rB & 7;

    load_stage(0, 0);
    load_stage(1, 1);

    for (int kc = 0; kc < 8; kc++) {
        const int s = kc & 1;
        if (kc >= 6) CP_WAIT0(); else CP_WAIT1();
        __syncthreads();

        const u32 Abase = smem + (u32)s * STAGE_B + (u32)rA * 128;
        const u32 Xbase = smem + (u32)s * STAGE_B + 16384 + (u32)rB * 128;

        #pragma unroll
        for (int ks = 0; ks < 4; ks++) {
            u32 a[4][4], b[2][4];
            #pragma unroll
            for (int mt = 0; mt < 4; mt++) {
                u32 addr = Abase + mt * 2048 + (u32)(((ks * 2 + cA) ^ sA) << 4);
                ldsm4(a[mt][0], a[mt][1], a[mt][2], a[mt][3], addr);
            }
            #pragma unroll
            for (int nt2 = 0; nt2 < 2; nt2++) {
                u32 addr = Xbase + nt2 * 2048 + (u32)(((ks * 2 + cB) ^ sB) << 4);
                ldsm4(b[nt2][0], b[nt2][1], b[nt2][2], b[nt2][3], addr);
            }
            #pragma unroll
            for (int mt = 0; mt < 4; mt++)
                #pragma unroll
                for (int nt = 0; nt < 4; nt++) {
                    u32 b0 = b[nt >> 1][(nt & 1) * 2];
                    u32 b1 = b[nt >> 1][(nt & 1) * 2 + 1];
                    mma16816(c[mt][nt], a[mt][0], a[mt][1], a[mt][2], a[mt][3], b0, b1);
                }
        }
        __syncthreads();
        if (kc + 2 < 8) load_stage(kc + 2, s);
    }

    // ---- epilogue: fp16 transpose via smem, write into g_D rows ----
    __half* trans = (__half*)smg;            // 64 cols x TRH halfs (17.4 KB)
    #pragma unroll
    for (int mt = 0; mt < 4; mt++) {
        int m = m_off + mt * 16 + (lane >> 2);
        #pragma unroll
        for (int nt = 0; nt < 4; nt++) {
            int col = n_off + nt * 8 + (lane & 3) * 2;
            trans[(col)     * TRH + m]     = __float2half(c[mt][nt][0]);
            trans[(col + 1) * TRH + m]     = __float2half(c[mt][nt][1]);
            trans[(col)     * TRH + m + 8] = __float2half(c[mt][nt][2]);
            trans[(col + 1) * TRH + m + 8] = __float2half(c[mt][nt][3]);
        }
    }
    __syncthreads();
    {
        const int col = tid >> 1;            // 0..63 local col
        const int seg = tid & 1;             // 64 nodes each (128 B)
        int col_g = ntile * 64 + col;
        int bb = col_g / 20, hh = col_g - bb * 20;
        int row = (mtile < 4) ? hh : (20 + hh);
        int node0 = (mtile & 3) * 128 + seg * 64;
        const uint4* src = (const uint4*)(trans + col * TRH + seg * 64);
        uint4* dst = (uint4*)(g_D + (size_t)bb * 64 * Nn + (size_t)row * Nn + node0);
        #pragma unroll
        for (int q = 0; q < 8; q++) dst[q] = src[q];
    }
}

// ---------------- gates: HMMA pre-activations + scalar tail (R12, FROZEN) --
#define GSM_BYTES 45312
#define P_STRIDE 264

__global__ void __launch_bounds__(256, 2) gates_kernel(
    const float* __restrict__ W5u, const float* __restrict__ Wout,
    float* __restrict__ out_t)
{
    extern __shared__ char smraw[];
    char* smg = (char*)(((uintptr_t)smraw + 127) & ~(uintptr_t)127);
    const u32 smem = smem_u32(smg);
    const u32 sD = smem;                    // D slice, then overlaid by P
    const u32 sW = smem + 33792;
    __half* P = (__half*)smg;               // overlay
    float* sWhu = (float*)(smg + 41984);
    float* sWo1 = (float*)(smg + 43584);

    const int tid = threadIdx.x;
    const int b = blockIdx.x;
    const int nhalf = blockIdx.y;           // 0 or 1: node range [nhalf*256, +256)
    const size_t db = (size_t)b * 64 * Nn;
    const size_t sb = (size_t)b * Hh * Nn;
    const int node0 = nhalf * 256;

    // stage D slice: 64 rows x 256 halfs (512B rows, swizzled)
    #pragma unroll
    for (int i = 0; i < 8; i++) {
        int idx = tid + i * 256;           // 0..2047 chunks of 16B
        int r = idx >> 5, cc = idx & 31;
        u32 dst = sD + r * 512 + (u32)(((cc ^ (r & 7)) & 31) << 4);
        cp16(dst, g_D + db + (size_t)r * Nn + node0 + cc * 8);
    }
    // Wcat (64x64 fp16, 128B rows, swizzled)
    #pragma unroll
    for (int i = 0; i < 2; i++) {
        int idx = tid + i * 256;           // 0..511
        int r = idx >> 3, cc = idx & 7;
        u32 dst = sW + r * 128 + (u32)((cc ^ (r & 7)) << 4);
        cp16(dst, g_Wcat + r * 64 + cc * 8);
    }
    for (int i = tid; i < 400; i += 256) {
        sWhu[i] = W5u[i];
        sWo1[i] = Wout[(i / 20) * 40 + (i % 20)];
    }
    CP_COMMIT();
    CP_WAIT0();
    __syncthreads();

    // ---- HMMA: P[64][256] = Wcat @ Dslice ----
    const int w = tid >> 5, lane = tid & 31;
    const int mq = w & 3;
    const int nb = (w >> 2) * 128;
    float c[16][4];
    {
        u32 a[4][4];
        {
            int row = mq * 16 + (lane & 15);
            #pragma unroll
            for (int ks = 0; ks < 4; ks++) {
                int kch = ks * 2 + (lane >> 4);
                u32 addr = sW + row * 128 + (u32)((kch ^ (row & 7)) << 4);
                ldsm4(a[ks][0], a[ks][1], a[ks][2], a[ks][3], addr);
            }
        }
        #pragma unroll
        for (int f = 0; f < 16; f++)
            #pragma unroll
            for (int q = 0; q < 4; q++) c[f][q] = 0.f;

        #pragma unroll
        for (int ks = 0; ks < 4; ks++) {
            int krow = ks * 16 + (lane & 15);
            u32 rowbase = sD + krow * 512;
            int sw = krow & 7;
            #pragma unroll
            for (int g = 0; g < 8; g++) {
                int chunk = ((nb + g * 16) >> 3) + (lane >> 4);
                u32 addr = rowbase + (u32)(((chunk ^ sw) & 31) << 4);
                u32 b0, b1, b2, b3;
                ldsm4t(b0, b1, b2, b3, addr);
                mma16816(c[2 * g],     a[ks][0], a[ks][1], a[ks][2], a[ks][3], b0, b1);
                mma16816(c[2 * g + 1], a[ks][0], a[ks][1], a[ks][2], a[ks][3], b2, b3);
            }
        }
    }
    __syncthreads();   // all warps done MMA reads of D

    // ---- read fn (rows 40-59) for my node from the D slice BEFORE overlay ----
    float fn[Hh];
    {
        const int cc = tid >> 3;
        const u32 off = (u32)((tid & 7) * 2);
        #pragma unroll
        for (int h = 0; h < Hh; h++) {
            int r = 40 + h;
            u32 addr = sD + r * 512 + (u32)(((cc ^ (r & 7)) & 31) << 4) + off;
            unsigned short hv;
            asm volatile("ld.shared.u16 %0, [%1];" : "=h"(hv) : "r"(addr));
            fn[h] = __half2float(*reinterpret_cast<__half*>(&hv));
        }
    }
    __syncthreads();   // fn reads done before P overlays D

    // write P to smem (fp16, stride 264 halfs -> conflict-free)
    #pragma unroll
    for (int f = 0; f < 16; f++) {
        int n = nb + (f >> 1) * 16 + (f & 1) * 8 + (lane & 3) * 2;
        int m = mq * 16 + (lane >> 2);
        *(__half2*)(P + m * P_STRIDE + n)       = __floats2half2_rn(c[f][0], c[f][1]);
        *(__half2*)(P + (m + 8) * P_STRIDE + n) = __floats2half2_rn(c[f][2], c[f][3]);
    }
    __syncthreads();

    // ---- scalar tail: one node per thread ----
    const int n = node0 + tid;

    u64 rf2[10];
    #pragma unroll
    for (int j = 0; j < 10; j++) {
        float r0 = sigmoid_fast(__half2float(P[(20 + 2 * j) * P_STRIDE + tid]));
        float r1 = sigmoid_fast(__half2float(P[(21 + 2 * j) * P_STRIDE + tid]));
        rf2[j] = pack2(r0 * fn[2 * j], r1 * fn[2 * j + 1]);
    }

    float fnew[Hh];
    #pragma unroll
    for (int h = 0; h < Hh; h++) {
        u64 acc = pack2(__half2float(P[(40 + h) * P_STRIDE + tid]), 0.f);
        const float4* wv = (const float4*)&sWhu[h * 20];
        #pragma unroll
        for (int q = 0; q < 5; q++) {
            float4 a = wv[q];
            acc = fma2(pack2(a.x, a.y), rf2[2 * q], acc);
            acc = fma2(pack2(a.z, a.w), rf2[2 * q + 1], acc);
        }
        float hv = tanh_fast(fsum2(acc));
        float zv = sigmoid_fast(__half2float(P[h * P_STRIDE + tid]));
        fnew[h] = fmaf(zv, hv - fn[h], fn[h]);
    }

    // write state (fp16 into g_D rows 40-59) — coalesced
    #pragma unroll
    for (int h = 0; h < Hh; h++)
        g_D[db + (size_t)(40 + h) * Nn + n] = __float2half(fnew[h]);

    // out = Wo1@fnew + xout
    u64 f2[10];
    #pragma unroll
    for (int j = 0; j < 10; j++) f2[j] = pack2(fnew[2 * j], fnew[2 * j + 1]);
    float o[Hh];
    #pragma unroll
    for (int h = 0; h < Hh; h++) {
        u64 acc = pack2(__half2float(g_xout[sb + (size_t)h * Nn + n]), 0.f);
        const float4* wv = (const float4*)&sWo1[h * 20];
        #pragma unroll
        for (int q = 0; q < 5; q++) {
            float4 a = wv[q];
            acc = fma2(pack2(a.x, a.y), f2[2 * q], acc);
            acc = fma2(pack2(a.z, a.w), f2[2 * q + 1], acc);
        }
        o[h] = fsum2(acc);
    }
    float4* op = (float4*)(out_t + ((size_t)b * Nn + n) * Hh);
    #pragma unroll
    for (int j = 0; j < 5; j++)
        op[j] = make_float4(o[4 * j], o[4 * j + 1], o[4 * j + 2], o[4 * j + 3]);
}

// ---------------- host ----------------
extern "C" void kernel_launch(void* const* d_in, const int* in_sizes, int n_in,
                              void* d_out, int out_size) {
    (void)in_sizes; (void)n_in; (void)out_size;
    const float* x    = (const float*)d_in[0];
    const float* A    = (const float*)d_in[1];
    const float* W3w  = (const float*)d_in[2];
    const float* W3u  = (const float*)d_in[3];
    const float* W4w  = (const float*)d_in[4];
    const float* W4u  = (const float*)d_in[5];
    const float* W5w  = (const float*)d_in[6];
    const float* W5u  = (const float*)d_in[7];
    const float* Wout = (const float*)d_in[8];
    const float* bo   = (const float*)d_in[9];
    float* out = (float*)d_out;

    const int gemm_smem = 2 * STAGE_B + 128;
    cudaFuncSetAttribute(gemm_kernel, cudaFuncAttributeMaxDynamicSharedMemorySize, gemm_smem);
    cudaFuncSetAttribute(gates_kernel, cudaFuncAttributeMaxDynamicSharedMemorySize, GSM_BYTES);

    conv_A_kernel<<<dim3(16, 16), dim3(32, 32)>>>(A);
    conv_W_kernel<<<16, 256>>>(W3w, W3u, W4w, W4u, W5w);
    conv_X_kernel<<<Bb, Nn>>>(x, Wout, bo);

    const size_t slab = (size_t)Bb * Nn * Hh;
    for (int t = 0; t < Tt; t++) {
        gemm_kernel<<<dim3(BH / 64, 8), 128, gemm_smem>>>();
        gates_kernel<<<dim3(Bb, 2), 256, GSM_BYTES>>>(W5u, Wout, out + (size_t)t * slab);
    }
}

// round 16
// speedup vs baseline: 1.0198x; 1.0198x over previous
#include <cuda_runtime.h>
#include <cuda_fp16.h>
#include <cstdint>

#define Bb 2048
#define Nn 512
#define Hh 20
#define Tt 3
#define BH (Bb * Hh)          // 40960 columns

typedef unsigned long long u64;
typedef unsigned int u32;

// ---------------- device scratch ----------------
__device__ __half g_Ast[2 * Nn * Nn];         // stacked [A; A^T] fp16, [1024][512]
// Unified per-batch operand tensor: [b][64 rows][512 nodes] fp16
//   rows 0-19: agg_in, 20-39: agg_out, 40-59: fn (state), 60-63: zeros
__device__ __half g_D[(size_t)Bb * 64 * Nn];
__device__ __half g_xout[(size_t)Bb * Hh * Nn]; // Wout[:,20:40]@x + b, fp16 [b][h][n]
__device__ __half g_Wcat[64 * 64];            // [Wz;Wr;Wh_av] padded, [m][k] fp16

// ---------------- helpers ----------------
__device__ __forceinline__ u32 smem_u32(const void* p) {
    u32 a; asm("{ .reg .u64 t; cvta.to.shared.u64 t, %1; cvt.u32.u64 %0, t; }"
               : "=r"(a) : "l"(p)); return a;
}
__device__ __forceinline__ u64 pack2(float lo, float hi) {
    u64 r; asm("mov.b64 %0, {%1, %2};" : "=l"(r) : "f"(lo), "f"(hi)); return r;
}
__device__ __forceinline__ void unpack2(u64 v, float& lo, float& hi) {
    asm("mov.b64 {%0, %1}, %2;" : "=f"(lo), "=f"(hi) : "l"(v));
}
__device__ __forceinline__ u64 fma2(u64 a, u64 b, u64 c) {
    u64 d; asm("fma.rn.f32x2 %0, %1, %2, %3;" : "=l"(d) : "l"(a), "l"(b), "l"(c)); return d;
}
__device__ __forceinline__ float fsum2(u64 v) { float a, b; unpack2(v, a, b); return a + b; }

__device__ __forceinline__ float tanh_fast(float x) {
    float y; asm("tanh.approx.f32 %0, %1;" : "=f"(y) : "f"(x)); return y;
}
__device__ __forceinline__ float sigmoid_fast(float x) {
    return fmaf(tanh_fast(0.5f * x), 0.5f, 0.5f);
}

__device__ __forceinline__ void cp16(u32 dst, const void* src) {
    asm volatile("cp.async.cg.shared.global [%0], [%1], 16;" :: "r"(dst), "l"(src) : "memory");
}
#define CP_COMMIT() asm volatile("cp.async.commit_group;" ::: "memory")
#define CP_WAIT1()  asm volatile("cp.async.wait_group 1;" ::: "memory")
#define CP_WAIT0()  asm volatile("cp.async.wait_group 0;" ::: "memory")

__device__ __forceinline__ void ldsm4(u32& r0, u32& r1, u32& r2, u32& r3, u32 addr) {
    asm volatile("ldmatrix.sync.aligned.m8n8.x4.shared.b16 {%0,%1,%2,%3}, [%4];"
                 : "=r"(r0), "=r"(r1), "=r"(r2), "=r"(r3) : "r"(addr));
}
__device__ __forceinline__ void ldsm4t(u32& r0, u32& r1, u32& r2, u32& r3, u32 addr) {
    asm volatile("ldmatrix.sync.aligned.m8n8.x4.trans.shared.b16 {%0,%1,%2,%3}, [%4];"
                 : "=r"(r0), "=r"(r1), "=r"(r2), "=r"(r3) : "r"(addr));
}
__device__ __forceinline__ void mma16816(float* c,
                                         u32 a0, u32 a1, u32 a2, u32 a3, u32 b0, u32 b1) {
    asm volatile("mma.sync.aligned.m16n8k16.row.col.f32.f16.f16.f32 "
                 "{%0,%1,%2,%3}, {%4,%5,%6,%7}, {%8,%9}, {%0,%1,%2,%3};"
                 : "+f"(c[0]), "+f"(c[1]), "+f"(c[2]), "+f"(c[3])
                 : "r"(a0), "r"(a1), "r"(a2), "r"(a3), "r"(b0), "r"(b1));
}

// ---------------- prep: A -> fp16 stacked [A; A^T] ----------------
__global__ void conv_A_kernel(const float* __restrict__ A) {
    __shared__ float t[32][33];
    int x = blockIdx.x * 32 + threadIdx.x;
    int y = blockIdx.y * 32 + threadIdx.y;
    float v = A[y * Nn + x];
    g_Ast[y * Nn + x] = __float2half(v);
    t[threadIdx.y][threadIdx.x] = v;
    __syncthreads();
    int xo = blockIdx.y * 32 + threadIdx.x;
    int yo = blockIdx.x * 32 + threadIdx.y;
    g_Ast[(Nn + yo) * Nn + xo] = __float2half(t[threadIdx.x][threadIdx.y]);
}

// ---------------- prep: Wcat [64 m][64 k] fp16 ----------------
__global__ void conv_W_kernel(const float* __restrict__ W3w, const float* __restrict__ W3u,
                              const float* __restrict__ W4w, const float* __restrict__ W4u,
                              const float* __restrict__ W5w) {
    int idx = blockIdx.x * 256 + threadIdx.x;   // 0..4095
    int m = idx >> 6, k = idx & 63;
    float v = 0.f;
    if (m < 20) {
        if (k < 40) v = W3w[m * 40 + k];
        else if (k < 60) v = W3u[m * 20 + (k - 40)];
    } else if (m < 40) {
        int h = m - 20;
        if (k < 40) v = W4w[h * 40 + k];
        else if (k < 60) v = W4u[h * 20 + (k - 40)];
    } else if (m < 60) {
        int h = m - 40;
        if (k < 40) v = W5w[h * 40 + k];
    }
    g_Wcat[idx] = __float2half(v);
}

// ---------------- prep: x -> fn/pad rows of g_D + g_xout (coalesced) -------
__global__ void __launch_bounds__(Nn) conv_X_kernel(const float* __restrict__ x,
                                                    const float* __restrict__ Wout,
                                                    const float* __restrict__ bout) {
    __shared__ float sx[Nn * Hh];          // 40 KB, [node][h]
    __shared__ float sWo2[Hh][Hh];
    __shared__ float sB[Hh];
    int b = blockIdx.x, n = threadIdx.x;
    for (int i = n; i < Hh * Hh; i += Nn) sWo2[i / Hh][i % Hh] = Wout[(i / Hh) * 40 + 20 + (i % Hh)];
    if (n < Hh) sB[n] = bout[n];
    {
        const float4* src = (const float4*)(x + (size_t)b * Nn * Hh);
        float4* dst = (float4*)sx;
        #pragma unroll
        for (int i = 0; i < 5; i++) dst[n + i * Nn] = src[n + i * Nn];
    }
    __syncthreads();

    float v[Hh];
    {
        const float4* xp = (const float4*)(sx + n * Hh);
        #pragma unroll
        for (int j = 0; j < 5; j++) {
            float4 q = xp[j];
            v[4 * j] = q.x; v[4 * j + 1] = q.y; v[4 * j + 2] = q.z; v[4 * j + 3] = q.w;
        }
    }
    const size_t sb = (size_t)b * Hh * Nn + n;
    const size_t db = (size_t)b * 64 * Nn + n;
    #pragma unroll
    for (int h = 0; h < Hh; h++) {
        g_D[db + (size_t)(40 + h) * Nn] = __float2half(v[h]);
        float s = sB[h];
        #pragma unroll
        for (int j = 0; j < Hh; j++) s = fmaf(sWo2[h][j], v[j], s);
        g_xout[sb + (size_t)h * Nn] = __float2half(s);
    }
    #pragma unroll
    for (int r = 60; r < 64; r++) g_D[db + (size_t)r * Nn] = __float2half(0.f);
}

// ---------------- HMMA GEMM: [A;A^T] @ X -> g_D rows 0-39 (R12, FROZEN) ----
// 256-thread CTAs, 2 CTAs/SM. CTA tile 128m x 128n, K-chunk 64, 3-stage ring.
#define STAGE_B 32768
#define TRH 136   // transpose buffer stride (halfs)

__global__ void __launch_bounds__(256, 2) gemm_kernel() {
    extern __shared__ char smraw[];
    char* smg = (char*)(((uintptr_t)smraw + 127) & ~(uintptr_t)127);
    const u32 smem = smem_u32(smg);
    const int tid = threadIdx.x;
    const int wid = tid >> 5;
    const int lane = tid & 31;
    const int ntile = blockIdx.x;    // 0..319
    const int mtile = blockIdx.y;    // 0..7  (<4: agg_in, >=4: agg_out)

    const int m_off = (wid & 1) * 64;
    const int n_off = (wid >> 1) * 32;

    auto load_stage = [&](int kc, int s) {
        const u32 base = smem + (u32)s * STAGE_B;
        #pragma unroll
        for (int i = 0; i < 8; i++) {
            int idx = tid + i * 256;       // 0..2047
            int t = idx >> 10;             // 0=A, 1=X
            int r = (idx >> 3) & 127;
            int c = idx & 7;
            u32 dst = base + t * 16384 + r * 128 + (u32)((c ^ (r & 7)) << 4);
            const __half* src;
            if (t == 0) {
                src = g_Ast + (size_t)(mtile * 128 + r) * Nn + kc * 64 + c * 8;
            } else {
                int col = ntile * 128 + r;
                int bb = col / 20, hh = col - bb * 20;
                src = g_D + (size_t)bb * 64 * Nn + (size_t)(40 + hh) * Nn + kc * 64 + c * 8;
            }
            cp16(dst, src);
        }
        CP_COMMIT();
    };

    float c[4][4][4];
    #pragma unroll
    for (int mt = 0; mt < 4; mt++)
        #pragma unroll
        for (int nt = 0; nt < 4; nt++)
            #pragma unroll
            for (int q = 0; q < 4; q++) c[mt][nt][q] = 0.f;

    const int rA = m_off + (lane & 15);
    const int cA = lane >> 4;
    const int sA = rA & 7;
    const int rB = n_off + ((lane >> 4) & 1) * 8 + (lane & 7);
    const int cB = (lane >> 3) & 1;
    const int sB = rB & 7;

    load_stage(0, 0);
    load_stage(1, 1);

    for (int kc = 0; kc < 8; kc++) {
        const int s = kc % 3;
        if (kc < 7) CP_WAIT1(); else CP_WAIT0();
        __syncthreads();                 // stage s arrived; stage (kc+2)%3 drained
        if (kc + 2 < 8) load_stage(kc + 2, (kc + 2) % 3);

        const u32 Abase = smem + (u32)s * STAGE_B + (u32)rA * 128;
        const u32 Xbase = smem + (u32)s * STAGE_B + 16384 + (u32)rB * 128;

        #pragma unroll
        for (int ks = 0; ks < 4; ks++) {
            u32 a[4][4], b[2][4];
            #pragma unroll
            for (int mt = 0; mt < 4; mt++) {
                u32 addr = Abase + mt * 2048 + (u32)(((ks * 2 + cA) ^ sA) << 4);
                ldsm4(a[mt][0], a[mt][1], a[mt][2], a[mt][3], addr);
            }
            #pragma unroll
            for (int nt2 = 0; nt2 < 2; nt2++) {
                u32 addr = Xbase + nt2 * 2048 + (u32)(((ks * 2 + cB) ^ sB) << 4);
                ldsm4(b[nt2][0], b[nt2][1], b[nt2][2], b[nt2][3], addr);
            }
            #pragma unroll
            for (int mt = 0; mt < 4; mt++)
                #pragma unroll
                for (int nt = 0; nt < 4; nt++) {
                    u32 b0 = b[nt >> 1][(nt & 1) * 2];
                    u32 b1 = b[nt >> 1][(nt & 1) * 2 + 1];
                    mma16816(c[mt][nt], a[mt][0], a[mt][1], a[mt][2], a[mt][3], b0, b1);
                }
        }
    }
    __syncthreads();   // all compute done before trans overlays stage memory

    // ---- epilogue: fp16 transpose via smem, write into g_D rows ----
    __half* trans = (__half*)smg;            // 128 cols x TRH halfs (34 KB)
    #pragma unroll
    for (int mt = 0; mt < 4; mt++) {
        int m = m_off + mt * 16 + (lane >> 2);
        #pragma unroll
        for (int nt = 0; nt < 4; nt++) {
            int col = n_off + nt * 8 + (lane & 3) * 2;
            trans[(col)     * TRH + m]     = __float2half(c[mt][nt][0]);
            trans[(col + 1) * TRH + m]     = __float2half(c[mt][nt][1]);
            trans[(col)     * TRH + m + 8] = __float2half(c[mt][nt][2]);
            trans[(col + 1) * TRH + m + 8] = __float2half(c[mt][nt][3]);
        }
    }
    __syncthreads();
    {
        const int col = tid >> 1;            // 0..127 local col
        const int seg = tid & 1;             // 64 nodes each (128 B)
        int col_g = ntile * 128 + col;
        int bb = col_g / 20, hh = col_g - bb * 20;
        int row = (mtile < 4) ? hh : (20 + hh);
        int node0 = (mtile & 3) * 128 + seg * 64;
        const uint4* src = (const uint4*)(trans + col * TRH + seg * 64);
        uint4* dst = (uint4*)(g_D + (size_t)bb * 64 * Nn + (size_t)row * Nn + node0);
        #pragma unroll
        for (int q = 0; q < 8; q++) dst[q] = src[q];
    }
}

// ---------------- gates: 128-thread CTAs, 4 CTAs/SM, grid (Bb, 4) ----------
// Each CTA handles 128 nodes of one batch. P has its own region (no overlay).
// smem: D 64x256B = 16384 | P 64x136 halfs = 17408 @16384 | Wcat 8192 @33792 |
//       Whu 1600 @41984 | Wo1 1600 @43584  => 45184 (+pad)
#define GSM_BYTES 45312
#define P_STRIDE 136

__global__ void __launch_bounds__(128, 4) gates_kernel(
    const float* __restrict__ W5u, const float* __restrict__ Wout,
    float* __restrict__ out_t)
{
    extern __shared__ char smraw[];
    char* smg = (char*)(((uintptr_t)smraw + 127) & ~(uintptr_t)127);
    const u32 smem = smem_u32(smg);
    const u32 sD = smem;
    __half* P = (__half*)(smg + 16384);
    const u32 sW = smem + 33792;
    float* sWhu = (float*)(smg + 41984);
    float* sWo1 = (float*)(smg + 43584);

    const int tid = threadIdx.x;
    const int b = blockIdx.x;
    const int nq = blockIdx.y;              // 0..3: node range [nq*128, +128)
    const size_t db = (size_t)b * 64 * Nn;
    const size_t sb = (size_t)b * Hh * Nn;
    const int node0 = nq * 128;

    // stage D slice: 64 rows x 128 halfs (256B rows, &15 swizzle)
    #pragma unroll
    for (int i = 0; i < 8; i++) {
        int idx = tid + i * 128;           // 0..1023 chunks of 16B
        int r = idx >> 4, cc = idx & 15;
        u32 dst = sD + r * 256 + (u32)(((cc ^ (r & 7)) & 15) << 4);
        cp16(dst, g_D + db + (size_t)r * Nn + node0 + cc * 8);
    }
    // Wcat (64x64 fp16, 128B rows, swizzled)
    #pragma unroll
    for (int i = 0; i < 4; i++) {
        int idx = tid + i * 128;           // 0..511
        int r = idx >> 3, cc = idx & 7;
        u32 dst = sW + r * 128 + (u32)((cc ^ (r & 7)) << 4);
        cp16(dst, g_Wcat + r * 64 + cc * 8);
    }
    for (int i = tid; i < 400; i += 128) {
        sWhu[i] = W5u[i];
        sWo1[i] = Wout[(i / 20) * 40 + (i % 20)];
    }
    CP_COMMIT();
    CP_WAIT0();
    __syncthreads();

    // ---- HMMA: P[64][128] = Wcat @ Dslice; warp w covers m-rows [16w,16w+16)
    const int w = tid >> 5, lane = tid & 31;
    float c[16][4];
    {
        u32 a[4][4];
        {
            int row = w * 16 + (lane & 15);
            #pragma unroll
            for (int ks = 0; ks < 4; ks++) {
                int kch = ks * 2 + (lane >> 4);
                u32 addr = sW + row * 128 + (u32)((kch ^ (row & 7)) << 4);
                ldsm4(a[ks][0], a[ks][1], a[ks][2], a[ks][3], addr);
            }
        }
        #pragma unroll
        for (int f = 0; f < 16; f++)
            #pragma unroll
            for (int q = 0; q < 4; q++) c[f][q] = 0.f;

        #pragma unroll
        for (int ks = 0; ks < 4; ks++) {
            int krow = ks * 16 + (lane & 15);
            u32 rowbase = sD + krow * 256;
            int sw = krow & 7;
            #pragma unroll
            for (int g = 0; g < 8; g++) {   // 8 groups of 16 cols = 128
                int chunk = 2 * g + (lane >> 4);
                u32 addr = rowbase + (u32)(((chunk ^ sw) & 15) << 4);
                u32 b0, b1, b2, b3;
                ldsm4t(b0, b1, b2, b3, addr);
                mma16816(c[2 * g],     a[ks][0], a[ks][1], a[ks][2], a[ks][3], b0, b1);
                mma16816(c[2 * g + 1], a[ks][0], a[ks][1], a[ks][2], a[ks][3], b2, b3);
            }
        }
    }
    // write P (separate region, no race with D)
    #pragma unroll
    for (int f = 0; f < 16; f++) {
        int n = (f >> 1) * 16 + (f & 1) * 8 + (lane & 3) * 2;
        int m = w * 16 + (lane >> 2);
        *(__half2*)(P + m * P_STRIDE + n)       = __floats2half2_rn(c[f][0], c[f][1]);
        *(__half2*)(P + (m + 8) * P_STRIDE + n) = __floats2half2_rn(c[f][2], c[f][3]);
    }
    __syncthreads();

    // ---- scalar tail: one node per thread ----
    const int n = node0 + tid;
    float fn[Hh];
    {
        const int cc = tid >> 3;
        const u32 off = (u32)((tid & 7) * 2);
        #pragma unroll
        for (int h = 0; h < Hh; h++) {
            int r = 40 + h;
            u32 addr = sD + r * 256 + (u32)(((cc ^ (r & 7)) & 15) << 4) + off;
            unsigned short hv;
            asm volatile("ld.shared.u16 %0, [%1];" : "=h"(hv) : "r"(addr));
            fn[h] = __half2float(*reinterpret_cast<__half*>(&hv));
        }
    }

    u64 rf2[10];
    #pragma unroll
    for (int j = 0; j < 10; j++) {
        float r0 = sigmoid_fast(__half2float(P[(20 + 2 * j) * P_STRIDE + tid]));
        float r1 = sigmoid_fast(__half2float(P[(21 + 2 * j) * P_STRIDE + tid]));
        rf2[j] = pack2(r0 * fn[2 * j], r1 * fn[2 * j + 1]);
    }

    float fnew[Hh];
    #pragma unroll
    for (int h = 0; h < Hh; h++) {
        u64 acc = pack2(__half2float(P[(40 + h) * P_STRIDE + tid]), 0.f);
        const float4* wv = (const float4*)&sWhu[h * 20];
        #pragma unroll
        for (int q = 0; q < 5; q++) {
            float4 a = wv[q];
            acc = fma2(pack2(a.x, a.y), rf2[2 * q], acc);
            acc = fma2(pack2(a.z, a.w), rf2[2 * q + 1], acc);
        }
        float hv = tanh_fast(fsum2(acc));
        float zv = sigmoid_fast(__half2float(P[h * P_STRIDE + tid]));
        fnew[h] = fmaf(zv, hv - fn[h], fn[h]);
    }

    // write state (fp16 into g_D rows 40-59) — coalesced
    #pragma unroll
    for (int h = 0; h < Hh; h++)
        g_D[db + (size_t)(40 + h) * Nn + n] = __float2half(fnew[h]);

    // out = Wo1@fnew + xout
    u64 f2[10];
    #pragma unroll
    for (int j = 0; j < 10; j++) f2[j] = pack2(fnew[2 * j], fnew[2 * j + 1]);
    float o[Hh];
    #pragma unroll
    for (int h = 0; h < Hh; h++) {
        u64 acc = pack2(__half2float(g_xout[sb + (size_t)h * Nn + n]), 0.f);
        const float4* wv = (const float4*)&sWo1[h * 20];
        #pragma unroll
        for (int q = 0; q < 5; q++) {
            float4 a = wv[q];
            acc = fma2(pack2(a.x, a.y), f2[2 * q], acc);
            acc = fma2(pack2(a.z, a.w), f2[2 * q + 1], acc);
        }
        o[h] = fsum2(acc);
    }
    float4* op = (float4*)(out_t + ((size_t)b * Nn + n) * Hh);
    #pragma unroll
    for (int j = 0; j < 5; j++)
        op[j] = make_float4(o[4 * j], o[4 * j + 1], o[4 * j + 2], o[4 * j + 3]);
}

// ---------------- host ----------------
extern "C" void kernel_launch(void* const* d_in, const int* in_sizes, int n_in,
                              void* d_out, int out_size) {
    (void)in_sizes; (void)n_in; (void)out_size;
    const float* x    = (const float*)d_in[0];
    const float* A    = (const float*)d_in[1];
    const float* W3w  = (const float*)d_in[2];
    const float* W3u  = (const float*)d_in[3];
    const float* W4w  = (const float*)d_in[4];
    const float* W4u  = (const float*)d_in[5];
    const float* W5w  = (const float*)d_in[6];
    const float* W5u  = (const float*)d_in[7];
    const float* Wout = (const float*)d_in[8];
    const float* bo   = (const float*)d_in[9];
    float* out = (float*)d_out;

    const int gemm_smem = 3 * STAGE_B + 128;
    cudaFuncSetAttribute(gemm_kernel, cudaFuncAttributeMaxDynamicSharedMemorySize, gemm_smem);
    cudaFuncSetAttribute(gates_kernel, cudaFuncAttributeMaxDynamicSharedMemorySize, GSM_BYTES);

    conv_A_kernel<<<dim3(16, 16), dim3(32, 32)>>>(A);
    conv_W_kernel<<<16, 256>>>(W3w, W3u, W4w, W4u, W5w);
    conv_X_kernel<<<Bb, Nn>>>(x, Wout, bo);

    const size_t slab = (size_t)Bb * Nn * Hh;
    for (int t = 0; t < Tt; t++) {
        gemm_kernel<<<dim3(BH / 128, 8), 256, gemm_smem>>>();
        gates_kernel<<<dim3(Bb, 4), 128, GSM_BYTES>>>(W5u, Wout, out + (size_t)t * slab);
    }
}

// round 17
// speedup vs baseline: 1.0251x; 1.0052x over previous
#include <cuda_runtime.h>
#include <cuda_fp16.h>
#include <cstdint>

#define Bb 2048
#define Nn 512
#define Hh 20
#define Tt 3
#define BH (Bb * Hh)          // 40960 columns

typedef unsigned long long u64;
typedef unsigned int u32;

// ---------------- device scratch ----------------
__device__ __half g_Ast[2 * Nn * Nn];         // stacked [A; A^T] fp16, [1024][512]
// Unified per-batch operand tensor: [b][64 rows][512 nodes] fp16
//   rows 0-19: agg_in, 20-39: agg_out, 40-59: fn (state), 60-63: zeros
__device__ __half g_D[(size_t)Bb * 64 * Nn];
__device__ __half g_xout[(size_t)Bb * Hh * Nn]; // Wout[:,20:40]@x + b, fp16 [b][h][n]
__device__ __half g_Wcat[64 * 64];            // [Wz;Wr;Wh_av] padded, [m][k] fp16

// ---------------- helpers ----------------
__device__ __forceinline__ u32 smem_u32(const void* p) {
    u32 a; asm("{ .reg .u64 t; cvta.to.shared.u64 t, %1; cvt.u32.u64 %0, t; }"
               : "=r"(a) : "l"(p)); return a;
}
__device__ __forceinline__ u64 pack2(float lo, float hi) {
    u64 r; asm("mov.b64 %0, {%1, %2};" : "=l"(r) : "f"(lo), "f"(hi)); return r;
}
__device__ __forceinline__ void unpack2(u64 v, float& lo, float& hi) {
    asm("mov.b64 {%0, %1}, %2;" : "=f"(lo), "=f"(hi) : "l"(v));
}
__device__ __forceinline__ u64 fma2(u64 a, u64 b, u64 c) {
    u64 d; asm("fma.rn.f32x2 %0, %1, %2, %3;" : "=l"(d) : "l"(a), "l"(b), "l"(c)); return d;
}
__device__ __forceinline__ float fsum2(u64 v) { float a, b; unpack2(v, a, b); return a + b; }

__device__ __forceinline__ float tanh_fast(float x) {
    float y; asm("tanh.approx.f32 %0, %1;" : "=f"(y) : "f"(x)); return y;
}
__device__ __forceinline__ float sigmoid_fast(float x) {
    return fmaf(tanh_fast(0.5f * x), 0.5f, 0.5f);
}

__device__ __forceinline__ void cp16(u32 dst, const void* src) {
    asm volatile("cp.async.cg.shared.global [%0], [%1], 16;" :: "r"(dst), "l"(src) : "memory");
}
#define CP_COMMIT() asm volatile("cp.async.commit_group;" ::: "memory")
#define CP_WAIT1()  asm volatile("cp.async.wait_group 1;" ::: "memory")
#define CP_WAIT0()  asm volatile("cp.async.wait_group 0;" ::: "memory")

__device__ __forceinline__ void ldsm4(u32& r0, u32& r1, u32& r2, u32& r3, u32 addr) {
    asm volatile("ldmatrix.sync.aligned.m8n8.x4.shared.b16 {%0,%1,%2,%3}, [%4];"
                 : "=r"(r0), "=r"(r1), "=r"(r2), "=r"(r3) : "r"(addr));
}
__device__ __forceinline__ void ldsm4t(u32& r0, u32& r1, u32& r2, u32& r3, u32 addr) {
    asm volatile("ldmatrix.sync.aligned.m8n8.x4.trans.shared.b16 {%0,%1,%2,%3}, [%4];"
                 : "=r"(r0), "=r"(r1), "=r"(r2), "=r"(r3) : "r"(addr));
}
__device__ __forceinline__ void mma16816(float* c,
                                         u32 a0, u32 a1, u32 a2, u32 a3, u32 b0, u32 b1) {
    asm volatile("mma.sync.aligned.m16n8k16.row.col.f32.f16.f16.f32 "
                 "{%0,%1,%2,%3}, {%4,%5,%6,%7}, {%8,%9}, {%0,%1,%2,%3};"
                 : "+f"(c[0]), "+f"(c[1]), "+f"(c[2]), "+f"(c[3])
                 : "r"(a0), "r"(a1), "r"(a2), "r"(a3), "r"(b0), "r"(b1));
}

// ---------------- prep 1: A -> fp16 stacked [A; A^T] ----------------
__global__ void conv_A_kernel(const float* __restrict__ A) {
    __shared__ float t[32][33];
    int x = blockIdx.x * 32 + threadIdx.x;
    int y = blockIdx.y * 32 + threadIdx.y;
    float v = A[y * Nn + x];
    g_Ast[y * Nn + x] = __float2half(v);
    t[threadIdx.y][threadIdx.x] = v;
    __syncthreads();
    int xo = blockIdx.y * 32 + threadIdx.x;
    int yo = blockIdx.x * 32 + threadIdx.y;
    g_Ast[(Nn + yo) * Nn + xo] = __float2half(t[threadIdx.x][threadIdx.y]);
}

// ---------------- prep 2: x -> fn/pad rows of g_D + g_xout + Wcat ----------
__global__ void __launch_bounds__(Nn) conv_X_kernel(const float* __restrict__ x,
                                                    const float* __restrict__ Wout,
                                                    const float* __restrict__ bout,
                                                    const float* __restrict__ W3w,
                                                    const float* __restrict__ W3u,
                                                    const float* __restrict__ W4w,
                                                    const float* __restrict__ W4u,
                                                    const float* __restrict__ W5w) {
    __shared__ float sx[Nn * Hh];          // 40 KB, [node][h]
    __shared__ float sWo2[Hh][Hh];
    __shared__ float sB[Hh];
    int b = blockIdx.x, n = threadIdx.x;

    // blocks 0-15 also convert Wcat (64x64 fp16)
    if (b < 16 && n < 256) {
        int idx = b * 256 + n;             // 0..4095
        int m = idx >> 6, k = idx & 63;
        float v = 0.f;
        if (m < 20) {
            if (k < 40) v = W3w[m * 40 + k];
            else if (k < 60) v = W3u[m * 20 + (k - 40)];
        } else if (m < 40) {
            int h = m - 20;
            if (k < 40) v = W4w[h * 40 + k];
            else if (k < 60) v = W4u[h * 20 + (k - 40)];
        } else if (m < 60) {
            int h = m - 40;
            if (k < 40) v = W5w[h * 40 + k];
        }
        g_Wcat[idx] = __float2half(v);
    }

    for (int i = n; i < Hh * Hh; i += Nn) sWo2[i / Hh][i % Hh] = Wout[(i / Hh) * 40 + 20 + (i % Hh)];
    if (n < Hh) sB[n] = bout[n];
    {
        const float4* src = (const float4*)(x + (size_t)b * Nn * Hh);
        float4* dst = (float4*)sx;
        #pragma unroll
        for (int i = 0; i < 5; i++) dst[n + i * Nn] = src[n + i * Nn];
    }
    __syncthreads();

    float v[Hh];
    {
        const float4* xp = (const float4*)(sx + n * Hh);
        #pragma unroll
        for (int j = 0; j < 5; j++) {
            float4 q = xp[j];
            v[4 * j] = q.x; v[4 * j + 1] = q.y; v[4 * j + 2] = q.z; v[4 * j + 3] = q.w;
        }
    }
    const size_t sb = (size_t)b * Hh * Nn + n;
    const size_t db = (size_t)b * 64 * Nn + n;
    #pragma unroll
    for (int h = 0; h < Hh; h++) {
        g_D[db + (size_t)(40 + h) * Nn] = __float2half(v[h]);
        float s = sB[h];
        #pragma unroll
        for (int j = 0; j < Hh; j++) s = fmaf(sWo2[h][j], v[j], s);
        g_xout[sb + (size_t)h * Nn] = __float2half(s);
    }
    #pragma unroll
    for (int r = 60; r < 64; r++) g_D[db + (size_t)r * Nn] = __float2half(0.f);
}

// ---------------- HMMA GEMM: [A;A^T] @ X -> g_D rows 0-39 (FROZEN) ---------
// 256-thread CTAs, 2 CTAs/SM. CTA tile 128m x 128n, K-chunk 64, 3-stage ring.
#define STAGE_B 32768
#define TRH 136   // transpose buffer stride (halfs)

__global__ void __launch_bounds__(256, 2) gemm_kernel() {
    extern __shared__ char smraw[];
    char* smg = (char*)(((uintptr_t)smraw + 127) & ~(uintptr_t)127);
    const u32 smem = smem_u32(smg);
    const int tid = threadIdx.x;
    const int wid = tid >> 5;
    const int lane = tid & 31;
    const int ntile = blockIdx.x;    // 0..319
    const int mtile = blockIdx.y;    // 0..7  (<4: agg_in, >=4: agg_out)

    const int m_off = (wid & 1) * 64;
    const int n_off = (wid >> 1) * 32;

    auto load_stage = [&](int kc, int s) {
        const u32 base = smem + (u32)s * STAGE_B;
        #pragma unroll
        for (int i = 0; i < 8; i++) {
            int idx = tid + i * 256;       // 0..2047
            int t = idx >> 10;             // 0=A, 1=X
            int r = (idx >> 3) & 127;
            int c = idx & 7;
            u32 dst = base + t * 16384 + r * 128 + (u32)((c ^ (r & 7)) << 4);
            const __half* src;
            if (t == 0) {
                src = g_Ast + (size_t)(mtile * 128 + r) * Nn + kc * 64 + c * 8;
            } else {
                int col = ntile * 128 + r;
                int bb = col / 20, hh = col - bb * 20;
                src = g_D + (size_t)bb * 64 * Nn + (size_t)(40 + hh) * Nn + kc * 64 + c * 8;
            }
            cp16(dst, src);
        }
        CP_COMMIT();
    };

    float c[4][4][4];
    #pragma unroll
    for (int mt = 0; mt < 4; mt++)
        #pragma unroll
        for (int nt = 0; nt < 4; nt++)
            #pragma unroll
            for (int q = 0; q < 4; q++) c[mt][nt][q] = 0.f;

    const int rA = m_off + (lane & 15);
    const int cA = lane >> 4;
    const int sA = rA & 7;
    const int rB = n_off + ((lane >> 4) & 1) * 8 + (lane & 7);
    const int cB = (lane >> 3) & 1;
    const int sB = rB & 7;

    load_stage(0, 0);
    load_stage(1, 1);

    for (int kc = 0; kc < 8; kc++) {
        const int s = kc % 3;
        if (kc < 7) CP_WAIT1(); else CP_WAIT0();
        __syncthreads();                 // stage s arrived; stage (kc+2)%3 drained
        if (kc + 2 < 8) load_stage(kc + 2, (kc + 2) % 3);

        const u32 Abase = smem + (u32)s * STAGE_B + (u32)rA * 128;
        const u32 Xbase = smem + (u32)s * STAGE_B + 16384 + (u32)rB * 128;

        #pragma unroll
        for (int ks = 0; ks < 4; ks++) {
            u32 a[4][4], b[2][4];
            #pragma unroll
            for (int mt = 0; mt < 4; mt++) {
                u32 addr = Abase + mt * 2048 + (u32)(((ks * 2 + cA) ^ sA) << 4);
                ldsm4(a[mt][0], a[mt][1], a[mt][2], a[mt][3], addr);
            }
            #pragma unroll
            for (int nt2 = 0; nt2 < 2; nt2++) {
                u32 addr = Xbase + nt2 * 2048 + (u32)(((ks * 2 + cB) ^ sB) << 4);
                ldsm4(b[nt2][0], b[nt2][1], b[nt2][2], b[nt2][3], addr);
            }
            #pragma unroll
            for (int mt = 0; mt < 4; mt++)
                #pragma unroll
                for (int nt = 0; nt < 4; nt++) {
                    u32 b0 = b[nt >> 1][(nt & 1) * 2];
                    u32 b1 = b[nt >> 1][(nt & 1) * 2 + 1];
                    mma16816(c[mt][nt], a[mt][0], a[mt][1], a[mt][2], a[mt][3], b0, b1);
                }
        }
    }
    __syncthreads();   // all compute done before trans overlays stage memory

    // ---- epilogue: fp16 transpose via smem, write into g_D rows ----
    __half* trans = (__half*)smg;            // 128 cols x TRH halfs (34 KB)
    #pragma unroll
    for (int mt = 0; mt < 4; mt++) {
        int m = m_off + mt * 16 + (lane >> 2);
        #pragma unroll
        for (int nt = 0; nt < 4; nt++) {
            int col = n_off + nt * 8 + (lane & 3) * 2;
            trans[(col)     * TRH + m]     = __float2half(c[mt][nt][0]);
            trans[(col + 1) * TRH + m]     = __float2half(c[mt][nt][1]);
            trans[(col)     * TRH + m + 8] = __float2half(c[mt][nt][2]);
            trans[(col + 1) * TRH + m + 8] = __float2half(c[mt][nt][3]);
        }
    }
    __syncthreads();
    {
        const int col = tid >> 1;            // 0..127 local col
        const int seg = tid & 1;             // 64 nodes each (128 B)
        int col_g = ntile * 128 + col;
        int bb = col_g / 20, hh = col_g - bb * 20;
        int row = (mtile < 4) ? hh : (20 + hh);
        int node0 = (mtile & 3) * 128 + seg * 64;
        const uint4* src = (const uint4*)(trans + col * TRH + seg * 64);
        uint4* dst = (uint4*)(g_D + (size_t)bb * 64 * Nn + (size_t)row * Nn + node0);
        #pragma unroll
        for (int q = 0; q < 8; q++) dst[q] = src[q];
    }
}

// ---------------- gates: 128-thread CTAs, 4 CTAs/SM, grid (Bb, 4) ----------
// smem: D 16384 | P 17408 @16384 | Wcat 8192 @33792 | Whu 1600 @41984 |
//       Wo1 1600 @43584 | Xout 5120 @45184  => 50304 (+pad)
#define GSM_BYTES 50432
#define P_STRIDE 136

__global__ void __launch_bounds__(128, 4) gates_kernel(
    const float* __restrict__ W5u, const float* __restrict__ Wout,
    float* __restrict__ out_t)
{
    extern __shared__ char smraw[];
    char* smg = (char*)(((uintptr_t)smraw + 127) & ~(uintptr_t)127);
    const u32 smem = smem_u32(smg);
    const u32 sD = smem;
    __half* P = (__half*)(smg + 16384);
    const u32 sW = smem + 33792;
    float* sWhu = (float*)(smg + 41984);
    float* sWo1 = (float*)(smg + 43584);
    __half* sXo = (__half*)(smg + 45184);   // [20][128]
    const u32 sXoA = smem + 45184;

    const int tid = threadIdx.x;
    const int b = blockIdx.x;
    const int nq = blockIdx.y;              // 0..3: node range [nq*128, +128)
    const size_t db = (size_t)b * 64 * Nn;
    const size_t sb = (size_t)b * Hh * Nn;
    const int node0 = nq * 128;

    // stage D slice: 64 rows x 128 halfs (256B rows, &15 swizzle)
    #pragma unroll
    for (int i = 0; i < 8; i++) {
        int idx = tid + i * 128;           // 0..1023 chunks of 16B
        int r = idx >> 4, cc = idx & 15;
        u32 dst = sD + r * 256 + (u32)(((cc ^ (r & 7)) & 15) << 4);
        cp16(dst, g_D + db + (size_t)r * Nn + node0 + cc * 8);
    }
    // xout slice: 20 rows x 128 halfs (unswizzled)
    #pragma unroll
    for (int i = 0; i < 3; i++) {
        int idx = tid + i * 128;           // 0..383, need <320
        if (idx < 320) {
            int r = idx >> 4, cc = idx & 15;
            cp16(sXoA + r * 256 + cc * 16, g_xout + sb + (size_t)r * Nn + node0 + cc * 8);
        }
    }
    // Wcat (64x64 fp16, 128B rows, swizzled)
    #pragma unroll
    for (int i = 0; i < 4; i++) {
        int idx = tid + i * 128;           // 0..511
        int r = idx >> 3, cc = idx & 7;
        u32 dst = sW + r * 128 + (u32)((cc ^ (r & 7)) << 4);
        cp16(dst, g_Wcat + r * 64 + cc * 8);
    }
    for (int i = tid; i < 400; i += 128) {
        sWhu[i] = W5u[i];
        sWo1[i] = Wout[(i / 20) * 40 + (i % 20)];
    }
    CP_COMMIT();
    CP_WAIT0();
    __syncthreads();

    // ---- HMMA: P[64][128] = Wcat @ Dslice; warp w covers m-rows [16w,16w+16)
    const int w = tid >> 5, lane = tid & 31;
    float c[16][4];
    {
        u32 a[4][4];
        {
            int row = w * 16 + (lane & 15);
            #pragma unroll
            for (int ks = 0; ks < 4; ks++) {
                int kch = ks * 2 + (lane >> 4);
                u32 addr = sW + row * 128 + (u32)((kch ^ (row & 7)) << 4);
                ldsm4(a[ks][0], a[ks][1], a[ks][2], a[ks][3], addr);
            }
        }
        #pragma unroll
        for (int f = 0; f < 16; f++)
            #pragma unroll
            for (int q = 0; q < 4; q++) c[f][q] = 0.f;

        #pragma unroll
        for (int ks = 0; ks < 4; ks++) {
            int krow = ks * 16 + (lane & 15);
            u32 rowbase = sD + krow * 256;
            int sw = krow & 7;
            #pragma unroll
            for (int g = 0; g < 8; g++) {   // 8 groups of 16 cols = 128
                int chunk = 2 * g + (lane >> 4);
                u32 addr = rowbase + (u32)(((chunk ^ sw) & 15) << 4);
                u32 b0, b1, b2, b3;
                ldsm4t(b0, b1, b2, b3, addr);
                mma16816(c[2 * g],     a[ks][0], a[ks][1], a[ks][2], a[ks][3], b0, b1);
                mma16816(c[2 * g + 1], a[ks][0], a[ks][1], a[ks][2], a[ks][3], b2, b3);
            }
        }
    }
    // write P (separate region, no race with D)
    #pragma unroll
    for (int f = 0; f < 16; f++) {
        int n = (f >> 1) * 16 + (f & 1) * 8 + (lane & 3) * 2;
        int m = w * 16 + (lane >> 2);
        *(__half2*)(P + m * P_STRIDE + n)       = __floats2half2_rn(c[f][0], c[f][1]);
        *(__half2*)(P + (m + 8) * P_STRIDE + n) = __floats2half2_rn(c[f][2], c[f][3]);
    }
    __syncthreads();

    // ---- scalar tail: one node per thread ----
    const int n = node0 + tid;
    float fn[Hh];
    {
        const int cc = tid >> 3;
        const u32 off = (u32)((tid & 7) * 2);
        #pragma unroll
        for (int h = 0; h < Hh; h++) {
            int r = 40 + h;
            u32 addr = sD + r * 256 + (u32)(((cc ^ (r & 7)) & 15) << 4) + off;
            unsigned short hv;
            asm volatile("ld.shared.u16 %0, [%1];" : "=h"(hv) : "r"(addr));
            fn[h] = __half2float(*reinterpret_cast<__half*>(&hv));
        }
    }

    u64 rf2[10];
    #pragma unroll
    for (int j = 0; j < 10; j++) {
        float r0 = sigmoid_fast(__half2float(P[(20 + 2 * j) * P_STRIDE + tid]));
        float r1 = sigmoid_fast(__half2float(P[(21 + 2 * j) * P_STRIDE + tid]));
        rf2[j] = pack2(r0 * fn[2 * j], r1 * fn[2 * j + 1]);
    }

    float fnew[Hh];
    #pragma unroll
    for (int h = 0; h < Hh; h++) {
        u64 acc = pack2(__half2float(P[(40 + h) * P_STRIDE + tid]), 0.f);
        const float4* wv = (const float4*)&sWhu[h * 20];
        #pragma unroll
        for (int q = 0; q < 5; q++) {
            float4 a = wv[q];
            acc = fma2(pack2(a.x, a.y), rf2[2 * q], acc);
            acc = fma2(pack2(a.z, a.w), rf2[2 * q + 1], acc);
        }
        float hv = tanh_fast(fsum2(acc));
        float zv = sigmoid_fast(__half2float(P[h * P_STRIDE + tid]));
        fnew[h] = fmaf(zv, hv - fn[h], fn[h]);
    }

    // write state (fp16 into g_D rows 40-59) — coalesced
    #pragma unroll
    for (int h = 0; h < Hh; h++)
        g_D[db + (size_t)(40 + h) * Nn + n] = __float2half(fnew[h]);

    // out = Wo1@fnew + xout (xout from smem stage)
    u64 f2[10];
    #pragma unroll
    for (int j = 0; j < 10; j++) f2[j] = pack2(fnew[2 * j], fnew[2 * j + 1]);
    float o[Hh];
    #pragma unroll
    for (int h = 0; h < Hh; h++) {
        u64 acc = pack2(__half2float(sXo[h * 128 + tid]), 0.f);
        const float4* wv = (const float4*)&sWo1[h * 20];
        #pragma unroll
        for (int q = 0; q < 5; q++) {
            float4 a = wv[q];
            acc = fma2(pack2(a.x, a.y), f2[2 * q], acc);
            acc = fma2(pack2(a.z, a.w), f2[2 * q + 1], acc);
        }
        o[h] = fsum2(acc);
    }
    float4* op = (float4*)(out_t + ((size_t)b * Nn + n) * Hh);
    #pragma unroll
    for (int j = 0; j < 5; j++)
        op[j] = make_float4(o[4 * j], o[4 * j + 1], o[4 * j + 2], o[4 * j + 3]);
}

// ---------------- host ----------------
extern "C" void kernel_launch(void* const* d_in, const int* in_sizes, int n_in,
                              void* d_out, int out_size) {
    (void)in_sizes; (void)n_in; (void)out_size;
    const float* x    = (const float*)d_in[0];
    const float* A    = (const float*)d_in[1];
    const float* W3w  = (const float*)d_in[2];
    const float* W3u  = (const float*)d_in[3];
    const float* W4w  = (const float*)d_in[4];
    const float* W4u  = (const float*)d_in[5];
    const float* W5w  = (const float*)d_in[6];
    const float* W5u  = (const float*)d_in[7];
    const float* Wout = (const float*)d_in[8];
    const float* bo   = (const float*)d_in[9];
    float* out = (float*)d_out;

    const int gemm_smem = 3 * STAGE_B + 128;
    cudaFuncSetAttribute(gemm_kernel, cudaFuncAttributeMaxDynamicSharedMemorySize, gemm_smem);
    cudaFuncSetAttribute(gates_kernel, cudaFuncAttributeMaxDynamicSharedMemorySize, GSM_BYTES);

    // launch order: 0 conv_A, 1 conv_X, 2 gemm, 3 gates (<- profiled slot)
    conv_A_kernel<<<dim3(16, 16), dim3(32, 32)>>>(A);
    conv_X_kernel<<<Bb, Nn>>>(x, Wout, bo, W3w, W3u, W4w, W4u, W5w);

    const size_t slab = (size_t)Bb * Nn * Hh;
    for (int t = 0; t < Tt; t++) {
        gemm_kernel<<<dim3(BH / 128, 8), 256, gemm_smem>>>();
        gates_kernel<<<dim3(Bb, 4), 128, GSM_BYTES>>>(W5u, Wout, out + (size_t)t * slab);
    }
}